// round 1
// baseline (speedup 1.0000x reference)
#include <cuda_runtime.h>

// Causal scaled-dot-product attention, fp32 flash-attention style.
// B=4, H=12, S=2048, D=64. Inputs (metadata order): keys, queries, values.
//
// One CTA = one (b*h, 64-row Q tile). 256 threads.
// Thread (R = tid>>4, C = tid&15):
//   QK phase: 4x4 score microtile, rows R*4+i, keys C+16*j
//   PV phase: 4 rows x 4 dims (dims 4*C .. 4*C+3), P via smem
// smem float4 stride 17 (68 floats) to avoid bank-group aliasing on K-row loads.

#define SEQ 2048
#define DH 64
#define NBH 48
#define STR4 17          // float4 stride per row (68 floats)
#define STRF 68

__global__ __launch_bounds__(256, 2)
void fa_fp32_kernel(const float* __restrict__ Kg_, const float* __restrict__ Qg_,
                    const float* __restrict__ Vg_, float* __restrict__ Og_) {
    extern __shared__ float4 smem4[];
    float4* Qs = smem4;                  // 64*17 float4
    float4* Ks = Qs + 64 * STR4;
    float4* Vs = Ks + 64 * STR4;
    float4* Ps = Vs + 64 * STR4;
    float*  Psf = reinterpret_cast<float*>(Ps);

    const int qt  = blockIdx.x;          // q tile index (0..31)
    const int bh  = blockIdx.y;          // 0..47
    const int tid = threadIdx.x;
    const int R   = tid >> 4;            // 0..15 (row group of 4)
    const int C   = tid & 15;            // 0..15

    const size_t base = (size_t)bh * SEQ * DH;
    const float4* Qg = reinterpret_cast<const float4*>(Qg_ + base);
    const float4* Kg = reinterpret_cast<const float4*>(Kg_ + base);
    const float4* Vg = reinterpret_cast<const float4*>(Vg_ + base);
    float4*       Og = reinterpret_cast<float4*>(Og_ + base);

    // ---- load Q tile ----
    #pragma unroll
    for (int it = 0; it < 4; it++) {
        int idx = tid + it * 256;        // 0..1023
        int row = idx >> 4, c4 = idx & 15;
        Qs[row * STR4 + c4] = Qg[(qt * 64 + row) * 16 + c4];
    }

    float m[4], l[4];
    float4 o4[4];
    #pragma unroll
    for (int i = 0; i < 4; i++) {
        m[i] = -3.0e38f; l[i] = 0.0f;
        o4[i] = make_float4(0.f, 0.f, 0.f, 0.f);
    }

    for (int kt = 0; kt <= qt; kt++) {
        __syncthreads();   // previous PV reads of V/P done before overwrite
        // ---- load K, V tiles ----
        #pragma unroll
        for (int it = 0; it < 4; it++) {
            int idx = tid + it * 256;
            int row = idx >> 4, c4 = idx & 15;
            Ks[row * STR4 + c4] = Kg[(kt * 64 + row) * 16 + c4];
            Vs[row * STR4 + c4] = Vg[(kt * 64 + row) * 16 + c4];
        }
        __syncthreads();

        // ---- scores: s[i][j] = Q[row R*4+i] . K[key C+16j] ----
        float s[4][4];
        #pragma unroll
        for (int i = 0; i < 4; i++)
            #pragma unroll
            for (int j = 0; j < 4; j++) s[i][j] = 0.f;

        #pragma unroll
        for (int d4 = 0; d4 < 16; d4++) {
            float4 q0 = Qs[(R * 4 + 0) * STR4 + d4];
            float4 q1 = Qs[(R * 4 + 1) * STR4 + d4];
            float4 q2 = Qs[(R * 4 + 2) * STR4 + d4];
            float4 q3 = Qs[(R * 4 + 3) * STR4 + d4];
            float4 k0 = Ks[(C +  0) * STR4 + d4];
            float4 k1 = Ks[(C + 16) * STR4 + d4];
            float4 k2 = Ks[(C + 32) * STR4 + d4];
            float4 k3 = Ks[(C + 48) * STR4 + d4];
            const float4 qv[4] = {q0, q1, q2, q3};
            const float4 kv[4] = {k0, k1, k2, k3};
            #pragma unroll
            for (int i = 0; i < 4; i++)
                #pragma unroll
                for (int j = 0; j < 4; j++) {
                    s[i][j] += qv[i].x * kv[j].x;
                    s[i][j] += qv[i].y * kv[j].y;
                    s[i][j] += qv[i].z * kv[j].z;
                    s[i][j] += qv[i].w * kv[j].w;
                }
        }

        // scale + causal mask (only diagonal tile needs masking)
        #pragma unroll
        for (int i = 0; i < 4; i++)
            #pragma unroll
            for (int j = 0; j < 4; j++) s[i][j] *= 0.125f;

        if (kt == qt) {
            #pragma unroll
            for (int i = 0; i < 4; i++) {
                int qrow = R * 4 + i;
                #pragma unroll
                for (int j = 0; j < 4; j++) {
                    int kcol = C + 16 * j;
                    if (kcol > qrow) s[i][j] = -3.0e38f;
                }
            }
        }

        // ---- online softmax update ----
        #pragma unroll
        for (int i = 0; i < 4; i++) {
            float rm = fmaxf(fmaxf(s[i][0], s[i][1]), fmaxf(s[i][2], s[i][3]));
            #pragma unroll
            for (int off = 8; off; off >>= 1)
                rm = fmaxf(rm, __shfl_xor_sync(0xffffffffu, rm, off));
            float mn = fmaxf(m[i], rm);
            float corr = __expf(m[i] - mn);
            float p0 = __expf(s[i][0] - mn);
            float p1 = __expf(s[i][1] - mn);
            float p2 = __expf(s[i][2] - mn);
            float p3 = __expf(s[i][3] - mn);
            float psum = (p0 + p1) + (p2 + p3);
            #pragma unroll
            for (int off = 8; off; off >>= 1)
                psum += __shfl_xor_sync(0xffffffffu, psum, off);
            l[i] = l[i] * corr + psum;
            m[i] = mn;
            o4[i].x *= corr; o4[i].y *= corr; o4[i].z *= corr; o4[i].w *= corr;
            // store P row segment to smem
            Psf[(R * 4 + i) * STRF + C +  0] = p0;
            Psf[(R * 4 + i) * STRF + C + 16] = p1;
            Psf[(R * 4 + i) * STRF + C + 32] = p2;
            Psf[(R * 4 + i) * STRF + C + 48] = p3;
        }
        __syncthreads();

        // ---- PV: o[i][dims 4C..4C+3] += sum_kk P[row][kk] * V[kk][dims] ----
        #pragma unroll 8
        for (int kk = 0; kk < 64; kk++) {
            float4 v = Vs[kk * STR4 + C];
            #pragma unroll
            for (int i = 0; i < 4; i++) {
                float p = Psf[(R * 4 + i) * STRF + kk];
                o4[i].x += p * v.x;
                o4[i].y += p * v.y;
                o4[i].z += p * v.z;
                o4[i].w += p * v.w;
            }
        }
    }

    // ---- epilogue: normalize + store ----
    #pragma unroll
    for (int i = 0; i < 4; i++) {
        float inv = 1.0f / l[i];
        o4[i].x *= inv; o4[i].y *= inv; o4[i].z *= inv; o4[i].w *= inv;
        Og[(qt * 64 + R * 4 + i) * 16 + C] = o4[i];
    }
}

extern "C" void kernel_launch(void* const* d_in, const int* in_sizes, int n_in,
                              void* d_out, int out_size) {
    const float* K = (const float*)d_in[0];   // keys
    const float* Q = (const float*)d_in[1];   // queries
    const float* V = (const float*)d_in[2];   // values
    float* O = (float*)d_out;

    size_t smem = 4ull * 64 * STR4 * sizeof(float4);  // 69632 bytes
    cudaFuncSetAttribute(fa_fp32_kernel,
                         cudaFuncAttributeMaxDynamicSharedMemorySize, (int)smem);

    dim3 grid(SEQ / 64, NBH);
    fa_fp32_kernel<<<grid, 256, (int)smem>>>(K, Q, V, O);
}

// round 2
// speedup vs baseline: 2.6243x; 2.6243x over previous
#include <cuda_runtime.h>
#include <cstdint>

// Causal SDPA, tf32 tensor-core flash attention (mma.sync.m16n8k8.tf32).
// B=4, H=12, S=2048, D=64. Inputs (metadata order): keys, queries, values.
//
// CTA = 128 threads (4 warps), Q tile 128 rows (32 rows per warp = 2 x m16),
// KV tile 64. Online softmax in registers; P routed through per-warp smem.
// smem strides chosen for conflict-free fragment LDS.

#define SEQ 2048
#define DH 64
#define QT 128
#define KT 64
#define QSTR 68   // floats per Q/P row
#define KSTR 68
#define VSTR 72
#define PSTR 68

__device__ __forceinline__ float tf32r(float x) {
    asm("cvt.rna.tf32.f32 %0, %0;" : "+f"(x));
    return x;
}

__device__ __forceinline__ void mma_tf32(float c[4],
                                         uint32_t a0, uint32_t a1, uint32_t a2, uint32_t a3,
                                         uint32_t b0, uint32_t b1) {
    asm volatile("mma.sync.aligned.m16n8k8.row.col.f32.tf32.tf32.f32 "
                 "{%0,%1,%2,%3}, {%4,%5,%6,%7}, {%8,%9}, {%0,%1,%2,%3};"
                 : "+f"(c[0]), "+f"(c[1]), "+f"(c[2]), "+f"(c[3])
                 : "r"(a0), "r"(a1), "r"(a2), "r"(a3), "r"(b0), "r"(b1));
}

__global__ __launch_bounds__(128)
void fa_tf32_kernel(const float* __restrict__ Kg_, const float* __restrict__ Qg_,
                    const float* __restrict__ Vg_, float* __restrict__ Og_)
{
    extern __shared__ float sm[];
    float* Qs = sm;                    // 128 x 68
    float* Ks = Qs + QT * QSTR;        // 64 x 68
    float* Vs = Ks + KT * KSTR;        // 64 x 72
    float* Ps = Vs + KT * VSTR;        // 128 x 68

    const int qt   = blockIdx.x;       // 0..15
    const int bh   = blockIdx.y;       // 0..47
    const int tid  = threadIdx.x;
    const int w    = tid >> 5;
    const int lane = tid & 31;
    const int lr   = lane >> 2;        // groupID 0..7
    const int lc   = lane & 3;         // threadInGroup 0..3

    const size_t base = (size_t)bh * SEQ * DH;
    const float4* Qg = (const float4*)(Qg_ + base);
    const float4* Kg = (const float4*)(Kg_ + base);
    const float4* Vg = (const float4*)(Vg_ + base);

    // ---- load Q tile (pre-scaled by 1/8, tf32 rna-rounded) ----
    #pragma unroll
    for (int i = 0; i < 16; i++) {
        int idx = tid + i * 128;            // 0..2047
        int row = idx >> 4, c4 = idx & 15;
        float4 q = Qg[(qt * QT + row) * 16 + c4];
        q.x = tf32r(q.x * 0.125f); q.y = tf32r(q.y * 0.125f);
        q.z = tf32r(q.z * 0.125f); q.w = tf32r(q.w * 0.125f);
        *(float4*)&Qs[row * QSTR + c4 * 4] = q;
    }

    float o[2][8][4];
    float m[2][2], l[2][2];
    #pragma unroll
    for (int mb = 0; mb < 2; mb++) {
        m[mb][0] = -1e30f; m[mb][1] = -1e30f;
        l[mb][0] = 0.f;    l[mb][1] = 0.f;
        #pragma unroll
        for (int n = 0; n < 8; n++)
            #pragma unroll
            for (int j = 0; j < 4; j++) o[mb][n][j] = 0.f;
    }

    const int ktmax    = 2 * qt + 2;
    const int wrow_min = qt * QT + w * 32;       // warp's min global q-row
    const int wrow_max = wrow_min + 31;

    const uint32_t* Qsu = (const uint32_t*)Qs;
    const uint32_t* Ksu = (const uint32_t*)Ks;
    const uint32_t* Vsu = (const uint32_t*)Vs;
    const uint32_t* Psu = (const uint32_t*)Ps;

    for (int kt = 0; kt < ktmax; kt++) {
        __syncthreads();     // prior tile's V/K reads complete
        // ---- load K, V tiles (tf32 rna-rounded) ----
        #pragma unroll
        for (int i = 0; i < 8; i++) {
            int idx = tid + i * 128;        // 0..1023
            int row = idx >> 4, c4 = idx & 15;
            float4 k = Kg[(kt * KT + row) * 16 + c4];
            k.x = tf32r(k.x); k.y = tf32r(k.y); k.z = tf32r(k.z); k.w = tf32r(k.w);
            *(float4*)&Ks[row * KSTR + c4 * 4] = k;
            float4 v = Vg[(kt * KT + row) * 16 + c4];
            v.x = tf32r(v.x); v.y = tf32r(v.y); v.z = tf32r(v.z); v.w = tf32r(v.w);
            *(float4*)&Vs[row * VSTR + c4 * 4] = v;
        }
        __syncthreads();

        if (kt * KT <= wrow_max) {                     // warp has unmasked keys
            const bool diag = (kt * KT + KT - 1 > wrow_min);   // partial masking needed
            #pragma unroll
            for (int mb = 0; mb < 2; mb++) {
                const int rl = w * 32 + mb * 16 + lr;  // local row (lo half)

                // ---- QK: S[16x64] for this mblk ----
                float s[8][4];
                #pragma unroll
                for (int n = 0; n < 8; n++)
                    #pragma unroll
                    for (int j = 0; j < 4; j++) s[n][j] = 0.f;

                #pragma unroll
                for (int k = 0; k < 8; k++) {
                    uint32_t a0 = Qsu[ rl      * QSTR + k * 8 + lc];
                    uint32_t a1 = Qsu[(rl + 8) * QSTR + k * 8 + lc];
                    uint32_t a2 = Qsu[ rl      * QSTR + k * 8 + lc + 4];
                    uint32_t a3 = Qsu[(rl + 8) * QSTR + k * 8 + lc + 4];
                    #pragma unroll
                    for (int n = 0; n < 8; n++) {
                        uint32_t b0 = Ksu[(n * 8 + lr) * KSTR + k * 8 + lc];
                        uint32_t b1 = Ksu[(n * 8 + lr) * KSTR + k * 8 + lc + 4];
                        mma_tf32(s[n], a0, a1, a2, a3, b0, b1);
                    }
                }

                // ---- causal mask (only near-diagonal tiles) ----
                if (diag) {
                    int qlo = qt * QT + rl;
                    int qhi = qlo + 8;
                    #pragma unroll
                    for (int n = 0; n < 8; n++) {
                        int key = kt * KT + n * 8 + 2 * lc;
                        if (key     > qlo) s[n][0] = -1e30f;
                        if (key + 1 > qlo) s[n][1] = -1e30f;
                        if (key     > qhi) s[n][2] = -1e30f;
                        if (key + 1 > qhi) s[n][3] = -1e30f;
                    }
                }

                // ---- online softmax (rows lo: c0,c1 ; hi: c2,c3) ----
                float rmx0 = -1e30f, rmx1 = -1e30f;
                #pragma unroll
                for (int n = 0; n < 8; n++) {
                    rmx0 = fmaxf(rmx0, fmaxf(s[n][0], s[n][1]));
                    rmx1 = fmaxf(rmx1, fmaxf(s[n][2], s[n][3]));
                }
                rmx0 = fmaxf(rmx0, __shfl_xor_sync(0xffffffffu, rmx0, 1));
                rmx0 = fmaxf(rmx0, __shfl_xor_sync(0xffffffffu, rmx0, 2));
                rmx1 = fmaxf(rmx1, __shfl_xor_sync(0xffffffffu, rmx1, 1));
                rmx1 = fmaxf(rmx1, __shfl_xor_sync(0xffffffffu, rmx1, 2));

                float mn0 = fmaxf(m[mb][0], rmx0);
                float mn1 = fmaxf(m[mb][1], rmx1);
                float corr0 = __expf(m[mb][0] - mn0);
                float corr1 = __expf(m[mb][1] - mn1);
                m[mb][0] = mn0; m[mb][1] = mn1;

                float ps0 = 0.f, ps1 = 0.f;
                #pragma unroll
                for (int n = 0; n < 8; n++) {
                    float p0 = __expf(s[n][0] - mn0);
                    float p1 = __expf(s[n][1] - mn0);
                    float p2 = __expf(s[n][2] - mn1);
                    float p3 = __expf(s[n][3] - mn1);
                    ps0 += p0 + p1;
                    ps1 += p2 + p3;
                    float2 lo2 = make_float2(tf32r(p0), tf32r(p1));
                    float2 hi2 = make_float2(tf32r(p2), tf32r(p3));
                    *(float2*)&Ps[ rl      * PSTR + n * 8 + 2 * lc] = lo2;
                    *(float2*)&Ps[(rl + 8) * PSTR + n * 8 + 2 * lc] = hi2;
                }
                ps0 += __shfl_xor_sync(0xffffffffu, ps0, 1);
                ps0 += __shfl_xor_sync(0xffffffffu, ps0, 2);
                ps1 += __shfl_xor_sync(0xffffffffu, ps1, 1);
                ps1 += __shfl_xor_sync(0xffffffffu, ps1, 2);
                l[mb][0] = l[mb][0] * corr0 + ps0;
                l[mb][1] = l[mb][1] * corr1 + ps1;

                #pragma unroll
                for (int n = 0; n < 8; n++) {
                    o[mb][n][0] *= corr0; o[mb][n][1] *= corr0;
                    o[mb][n][2] *= corr1; o[mb][n][3] *= corr1;
                }

                __syncwarp();   // P rows are warp-private; order STS before LDS

                // ---- PV: O[16x64] += P[16x64] * V[64x64] ----
                #pragma unroll
                for (int k = 0; k < 8; k++) {
                    uint32_t a0 = Psu[ rl      * PSTR + k * 8 + lc];
                    uint32_t a1 = Psu[(rl + 8) * PSTR + k * 8 + lc];
                    uint32_t a2 = Psu[ rl      * PSTR + k * 8 + lc + 4];
                    uint32_t a3 = Psu[(rl + 8) * PSTR + k * 8 + lc + 4];
                    #pragma unroll
                    for (int n = 0; n < 8; n++) {
                        uint32_t b0 = Vsu[(k * 8 + lc)     * VSTR + n * 8 + lr];
                        uint32_t b1 = Vsu[(k * 8 + lc + 4) * VSTR + n * 8 + lr];
                        mma_tf32(o[mb][n], a0, a1, a2, a3, b0, b1);
                    }
                }
                __syncwarp();   // PV reads done before next mb overwrites Ps rows? (different rows; kept for safety vs next tile)
            }
        }
    }

    // ---- epilogue: normalize + store (float2, cols 2lc..2lc+1 of each nblk) ----
    float2* Og = (float2*)(Og_ + base);
    #pragma unroll
    for (int mb = 0; mb < 2; mb++) {
        float inv0 = 1.0f / l[mb][0];
        float inv1 = 1.0f / l[mb][1];
        int grow = qt * QT + w * 32 + mb * 16 + lr;
        #pragma unroll
        for (int n = 0; n < 8; n++) {
            Og[ grow      * 32 + n * 4 + lc] = make_float2(o[mb][n][0] * inv0, o[mb][n][1] * inv0);
            Og[(grow + 8) * 32 + n * 4 + lc] = make_float2(o[mb][n][2] * inv1, o[mb][n][3] * inv1);
        }
    }
}

extern "C" void kernel_launch(void* const* d_in, const int* in_sizes, int n_in,
                              void* d_out, int out_size) {
    const float* K = (const float*)d_in[0];   // keys
    const float* Q = (const float*)d_in[1];   // queries
    const float* V = (const float*)d_in[2];   // values
    float* O = (float*)d_out;

    size_t smem = (size_t)(QT * QSTR + KT * KSTR + KT * VSTR + QT * PSTR) * sizeof(float);
    cudaFuncSetAttribute(fa_tf32_kernel,
                         cudaFuncAttributeMaxDynamicSharedMemorySize, (int)smem);

    dim3 grid(SEQ / QT, 48);
    fa_tf32_kernel<<<grid, 128, (int)smem>>>(K, Q, V, O);
}